// round 1
// baseline (speedup 1.0000x reference)
#include <cuda_runtime.h>
#include <cstdint>

#define AD   64      // ATOM_DIM
#define BD   16      // BOND_DIM
#define BD1  17      // BOND_DIM + 1 (bias folded in)
#define TM   128     // edges per CTA tile
#define NBP  68      // nbf smem row pitch (floats): conflict-free A preload, 16B-aligned rows
#define WBP  72      // W smem row pitch (floats): 72%32=8 -> conflict-free B frag loads

// Packed weight: W_g[k'][i] with k' = b*64 + j, value = K[b, i*64+j] (b<16) or bias[i*64+j] (b=16).
// Pre-rounded to tf32.
__device__ float W_g[BD1 * AD * AD];

__device__ __forceinline__ uint32_t f2tf32(float x) {
    uint32_t r;
    asm("cvt.rna.tf32.f32 %0, %1;" : "=r"(r) : "f"(x));
    return r;
}

__device__ __forceinline__ void cp_async16(void* smem, const void* gmem) {
    uint32_t s = (uint32_t)__cvta_generic_to_shared(smem);
    asm volatile("cp.async.cg.shared.global [%0], [%1], 16;\n" :: "r"(s), "l"(gmem));
}
__device__ __forceinline__ void cp_commit() { asm volatile("cp.async.commit_group;\n"); }
template <int N> __device__ __forceinline__ void cp_wait() {
    asm volatile("cp.async.wait_group %0;\n" :: "n"(N));
}

__global__ void pack_w_kernel(const float* __restrict__ K, const float* __restrict__ bias) {
    int idx = blockIdx.x * blockDim.x + threadIdx.x;
    if (idx >= BD1 * AD * AD) return;
    int i  = idx & 63;
    int kp = idx >> 6;       // k' = b*64 + j
    int j  = kp & 63;
    int b  = kp >> 6;
    float v = (b < BD) ? K[b * AD * AD + i * AD + j] : bias[i * AD + j];
    W_g[idx] = __uint_as_float(f2tf32(v));
}

// GEMM-formulated edge network:
//   out[src[e], i] += sum_{b,j} bond17[e,b] * nbf[e,j] * W[b*64+j, i]
// A (Z) is built on the fly: per b-block, A-frag = nbf-frag scaled per-row by bond[e,b].
__global__ void __launch_bounds__(256)
edge_main(const float* __restrict__ atom, const float* __restrict__ bondf,
          const int* __restrict__ pair, float* __restrict__ out, int n_edges)
{
    extern __shared__ float sm[];
    float* nbf_s  = sm;                         // [TM][NBP]
    float* wb_s   = sm + TM * NBP;              // [2][64][WBP]
    float* bond_s = wb_s + 2 * 64 * WBP;        // [BD1][TM]
    int*   src_s  = (int*)(bond_s + BD1 * TM);  // [TM]
    int*   nbr_s  = src_s + TM;                 // [TM]

    const int tid  = threadIdx.x;
    const int warp = tid >> 5, lane = tid & 31;
    const int gid  = lane >> 2, tig = lane & 3;
    const int e0   = blockIdx.x * TM;

    // Stage W for b=0 immediately (no dependencies).
    for (int idx = tid; idx < 1024; idx += 256) {
        int k = idx >> 4, q = idx & 15;
        cp_async16(wb_s + k * WBP + q * 4, W_g + k * 64 + q * 4);
    }
    cp_commit();

    // Pair indices + implicit bias-lane of bond17.
    if (tid < TM) {
        int e = e0 + tid;
        int src = -1, nb = -1; float onef = 0.f;
        if (e < n_edges) { int2 p = ((const int2*)pair)[e]; src = p.x; nb = p.y; onef = 1.f; }
        src_s[tid] = src; nbr_s[tid] = nb;
        bond_s[BD * TM + tid] = onef;
    }
    // Bond tile (coalesced).
    for (int idx = tid; idx < TM * BD; idx += 256) {
        int el = idx >> 4, bb = idx & 15;
        float v = (e0 + el < n_edges) ? bondf[(size_t)e0 * BD + idx] : 0.f;
        bond_s[bb * TM + el] = v;
    }
    __syncthreads();   // nbr_s ready

    // Gather neighbor features (128 rows x 64 f32, float4).
    for (int idx = tid; idx < TM * 16; idx += 256) {
        int el = idx >> 4, q = idx & 15;
        int nb = nbr_s[el];
        float4 v = make_float4(0.f, 0.f, 0.f, 0.f);
        if (nb >= 0) v = ((const float4*)atom)[(size_t)nb * 16 + q];
        *(float4*)(nbf_s + el * NBP + q * 4) = v;
    }
    __syncthreads();

    // Preload this thread's A-source values: all 17 b-blocks reuse these registers.
    const int mrow = warp * 16;
    const int r0 = mrow + gid, r1 = r0 + 8;
    float anb0[16], anb1[16];
    #pragma unroll
    for (int t = 0; t < 16; t++) {
        anb0[t] = nbf_s[r0 * NBP + tig + 4 * t];
        anb1[t] = nbf_s[r1 * NBP + tig + 4 * t];
    }

    float c[8][4];
    #pragma unroll
    for (int nt = 0; nt < 8; nt++)
        c[nt][0] = c[nt][1] = c[nt][2] = c[nt][3] = 0.f;

    for (int b = 0; b < BD1; b++) {
        // Prefetch next W block into the other buffer.
        if (b + 1 < BD1) {
            float* wbn = wb_s + ((b + 1) & 1) * (64 * WBP);
            for (int idx = tid; idx < 1024; idx += 256) {
                int k = idx >> 4, q = idx & 15;
                cp_async16(wbn + k * WBP + q * 4, W_g + ((b + 1) * 64 + k) * 64 + q * 4);
            }
            cp_commit();
            cp_wait<1>();
        } else {
            cp_wait<0>();
        }
        __syncthreads();

        const float* wb = wb_s + (b & 1) * (64 * WBP);
        const float sb0 = bond_s[b * TM + r0];
        const float sb1 = bond_s[b * TM + r1];

        #pragma unroll
        for (int kk = 0; kk < 8; kk++) {
            // A fragment of Z = bond-scaled nbf, rounded once (rna) to tf32.
            uint32_t a0 = f2tf32(anb0[2 * kk]     * sb0);
            uint32_t a1 = f2tf32(anb1[2 * kk]     * sb1);
            uint32_t a2 = f2tf32(anb0[2 * kk + 1] * sb0);
            uint32_t a3 = f2tf32(anb1[2 * kk + 1] * sb1);
            #pragma unroll
            for (int nt = 0; nt < 8; nt++) {
                uint32_t b0 = __float_as_uint(wb[(kk * 8 + tig)     * WBP + nt * 8 + gid]);
                uint32_t b1 = __float_as_uint(wb[(kk * 8 + tig + 4) * WBP + nt * 8 + gid]);
                asm volatile(
                    "mma.sync.aligned.m16n8k8.row.col.f32.tf32.tf32.f32 "
                    "{%0,%1,%2,%3}, {%4,%5,%6,%7}, {%8,%9}, {%0,%1,%2,%3};\n"
                    : "+f"(c[nt][0]), "+f"(c[nt][1]), "+f"(c[nt][2]), "+f"(c[nt][3])
                    : "r"(a0), "r"(a1), "r"(a2), "r"(a3), "r"(b0), "r"(b1));
            }
        }
        __syncthreads();   // protect wb buffer before it is restaged at b+2
    }

    // Epilogue: segment-sum via global float atomics, straight from registers.
    const int s0 = src_s[r0], s1 = src_s[r1];
    #pragma unroll
    for (int nt = 0; nt < 8; nt++) {
        int col = nt * 8 + tig * 2;
        if (s0 >= 0) {
            atomicAdd(out + (size_t)s0 * AD + col,     c[nt][0]);
            atomicAdd(out + (size_t)s0 * AD + col + 1, c[nt][1]);
        }
        if (s1 >= 0) {
            atomicAdd(out + (size_t)s1 * AD + col,     c[nt][2]);
            atomicAdd(out + (size_t)s1 * AD + col + 1, c[nt][3]);
        }
    }
}

extern "C" void kernel_launch(void* const* d_in, const int* in_sizes, int n_in,
                              void* d_out, int out_size) {
    const float* atom  = (const float*)d_in[0];
    const float* bondf = (const float*)d_in[1];
    const int*   pair  = (const int*)d_in[2];
    const float* K     = (const float*)d_in[3];
    const float* bias  = (const float*)d_in[4];
    float* out = (float*)d_out;

    int n_edges = in_sizes[2] / 2;

    cudaMemsetAsync(d_out, 0, (size_t)out_size * sizeof(float), 0);

    pack_w_kernel<<<(BD1 * AD * AD + 255) / 256, 256>>>(K, bias);

    int smem_bytes = (TM * NBP + 2 * 64 * WBP + BD1 * TM) * (int)sizeof(float)
                   + 2 * TM * (int)sizeof(int);
    cudaFuncSetAttribute(edge_main, cudaFuncAttributeMaxDynamicSharedMemorySize, smem_bytes);

    int grid = (n_edges + TM - 1) / TM;
    edge_main<<<grid, 256, smem_bytes>>>(atom, bondf, pair, out, n_edges);
}

// round 3
// speedup vs baseline: 1.8713x; 1.8713x over previous
#include <cuda_runtime.h>
#include <cuda_fp16.h>
#include <cstdint>

#define TM      128
#define NBLK    17
#define WPITCH  72                 // uint32 pitch per k-pair row (conflict-free: bank = 8*tig+gid)
#define WBLK_U  (32 * WPITCH)      // 2304 uints = 9216 B per b-block
#define WBLK_V4 (WBLK_U / 4)       // 576 uint4 chunks

// W image in fp16x2, pre-laid-out exactly as the smem tile (pitch-72), so cp.async is a linear copy.
// Wp[b][p][n] = half2{ W(b, k=2p, n), W(b, k=2p+1, n) }, W(b,j,i) = K[b, i*64+j] (b<16) | bias[i*64+j]
__device__ uint4 W_img[NBLK * WBLK_V4];

static __device__ __forceinline__ void cp_async16(void* s, const void* g) {
    uint32_t sa = (uint32_t)__cvta_generic_to_shared(s);
    asm volatile("cp.async.cg.shared.global [%0], [%1], 16;" :: "r"(sa), "l"(g));
}
static __device__ __forceinline__ uint32_t h2u(__half2 h) {
    return *reinterpret_cast<uint32_t*>(&h);
}
static __device__ __forceinline__ void mma16816(float* c, uint32_t a0, uint32_t a1,
                                                uint32_t a2, uint32_t a3,
                                                uint32_t b0, uint32_t b1) {
    asm volatile(
        "mma.sync.aligned.m16n8k16.row.col.f32.f16.f16.f32 "
        "{%0,%1,%2,%3}, {%4,%5,%6,%7}, {%8,%9}, {%0,%1,%2,%3};"
        : "+f"(c[0]), "+f"(c[1]), "+f"(c[2]), "+f"(c[3])
        : "r"(a0), "r"(a1), "r"(a2), "r"(a3), "r"(b0), "r"(b1));
}
static __device__ __forceinline__ void red4(float* p, float a, float b, float c, float d) {
    asm volatile("red.global.add.v4.f32 [%0], {%1, %2, %3, %4};"
                 :: "l"(p), "f"(a), "f"(b), "f"(c), "f"(d) : "memory");
}

__global__ void __launch_bounds__(256)
pack_w(const float* __restrict__ K, const float* __restrict__ bias) {
    int idx = blockIdx.x * blockDim.x + threadIdx.x;           // over 17*2048 half2 entries
    if (idx >= NBLK * 2048) return;
    int b = idx >> 11, r = idx & 2047;
    int p = r >> 6, n = r & 63;                                // k-pair p, col n
    int j0 = 2 * p, j1 = 2 * p + 1;
    float v0, v1;
    if (b < 16) { v0 = K[b * 4096 + n * 64 + j0]; v1 = K[b * 4096 + n * 64 + j1]; }
    else        { v0 = bias[n * 64 + j0];          v1 = bias[n * 64 + j1]; }
    __half2 h = __floats2half2_rn(v0, v1);
    ((uint32_t*)W_img)[b * WBLK_U + p * WPITCH + n] = h2u(h);
}

// GEMM-formulated edge network, fp16 m16n8k16, M=32 per warp (two m-tiles share B frags).
__global__ void __launch_bounds__(128, 3)
edge_main(const float* __restrict__ atom, const float* __restrict__ bondf,
          const int* __restrict__ pair, float* __restrict__ out, int n_edges)
{
    __shared__ uint32_t Wp[2][WBLK_U];          // 18432 B
    __shared__ float    bond_s[NBLK][TM];       // 8704 B
    __shared__ int      src_s[TM];
    __shared__ int      nbr_s[TM];

    const int tid  = threadIdx.x;
    const int warp = tid >> 5, lane = tid & 31;
    const int gid  = lane >> 2, tig = lane & 3;
    const int e0   = blockIdx.x * TM;

    // Kick W_0, W_1 staging immediately.
    #pragma unroll
    for (int g = 0; g < 2; g++) {
        for (int i = tid; i < WBLK_V4; i += 128)
            cp_async16(&Wp[g][i * 4], &W_img[g * WBLK_V4 + i]);
        asm volatile("cp.async.commit_group;");
    }

    // Stage pair indices + bond tile (one thread per edge row).
    {
        int e = e0 + tid;
        int src = -1, nbr = 0;
        float4 q0 = {0,0,0,0}, q1 = q0, q2 = q0, q3 = q0;
        float one = 0.f;
        if (e < n_edges) {
            int2 pr = ((const int2*)pair)[e];
            src = pr.x; nbr = pr.y; one = 1.f;
            const float4* bp = (const float4*)(bondf + (size_t)e * 16);
            q0 = bp[0]; q1 = bp[1]; q2 = bp[2]; q3 = bp[3];
        }
        src_s[tid] = src; nbr_s[tid] = nbr;
        bond_s[0][tid]  = q0.x; bond_s[1][tid]  = q0.y; bond_s[2][tid]  = q0.z; bond_s[3][tid]  = q0.w;
        bond_s[4][tid]  = q1.x; bond_s[5][tid]  = q1.y; bond_s[6][tid]  = q1.z; bond_s[7][tid]  = q1.w;
        bond_s[8][tid]  = q2.x; bond_s[9][tid]  = q2.y; bond_s[10][tid] = q2.z; bond_s[11][tid] = q2.w;
        bond_s[12][tid] = q3.x; bond_s[13][tid] = q3.y; bond_s[14][tid] = q3.z; bond_s[15][tid] = q3.w;
        bond_s[16][tid] = one;                           // folded bias lane
    }
    __syncthreads();

    // Rows owned by this thread: warp*32 + {gid, gid+8, gid+16, gid+24}.
    int rowI[4];
    rowI[0] = warp * 32 + gid;  rowI[1] = rowI[0] + 8;
    rowI[2] = rowI[0] + 16;     rowI[3] = rowI[0] + 24;

    // Neighbor features straight gmem -> half2 registers (single rn rounding).
    // nb[r][q] = half2{ atom[nbr][8q+2tig], atom[nbr][8q+2tig+1] }
    __half2 nb[4][8];
    #pragma unroll
    for (int r = 0; r < 4; r++) {
        const float2* ap = (const float2*)(atom + (size_t)nbr_s[rowI[r]] * 64);
        #pragma unroll
        for (int q = 0; q < 8; q++) {
            float2 v = __ldg(ap + 4 * q + tig);
            nb[r][q] = __floats2half2_rn(v.x, v.y);
        }
    }

    float c[2][8][4];
    #pragma unroll
    for (int m = 0; m < 2; m++)
        #pragma unroll
        for (int nt = 0; nt < 8; nt++)
            c[m][nt][0] = c[m][nt][1] = c[m][nt][2] = c[m][nt][3] = 0.f;

    for (int b = 0; b < NBLK; b++) {
        asm volatile("cp.async.wait_group 1;" ::: "memory");   // W_b resident
        __syncthreads();

        __half2 bh[4];
        #pragma unroll
        for (int r = 0; r < 4; r++) bh[r] = __float2half2_rn(bond_s[b][rowI[r]]);

        const uint32_t* W = Wp[b & 1];
        #pragma unroll
        for (int s = 0; s < 4; s++) {
            // A fragments: Z = bond-scaled neighbor features (fp16).
            uint32_t a00 = h2u(__hmul2(nb[0][2*s],   bh[0]));
            uint32_t a01 = h2u(__hmul2(nb[1][2*s],   bh[1]));
            uint32_t a02 = h2u(__hmul2(nb[0][2*s+1], bh[0]));
            uint32_t a03 = h2u(__hmul2(nb[1][2*s+1], bh[1]));
            uint32_t a10 = h2u(__hmul2(nb[2][2*s],   bh[2]));
            uint32_t a11 = h2u(__hmul2(nb[3][2*s],   bh[3]));
            uint32_t a12 = h2u(__hmul2(nb[2][2*s+1], bh[2]));
            uint32_t a13 = h2u(__hmul2(nb[3][2*s+1], bh[3]));
            #pragma unroll
            for (int nt = 0; nt < 8; nt++) {
                uint32_t b0 = W[(8*s + tig)     * WPITCH + nt*8 + gid];
                uint32_t b1 = W[(8*s + tig + 4) * WPITCH + nt*8 + gid];
                mma16816(c[0][nt], a00, a01, a02, a03, b0, b1);
                mma16816(c[1][nt], a10, a11, a12, a13, b0, b1);
            }
        }
        __syncthreads();

        if (b + 2 < NBLK) {
            for (int i = tid; i < WBLK_V4; i += 128)
                cp_async16(&Wp[b & 1][i * 4], &W_img[(b + 2) * WBLK_V4 + i]);
        }
        asm volatile("cp.async.commit_group;");   // one group per iteration keeps counts aligned
    }

    // Epilogue: pair-shuffle to form 4-consecutive-col quads, then vectorized global RED.
    // even tig -> rowA quad, odd tig -> rowB quad; colbase = nt*8 + 4*(tig>>1).
    const bool even = (tig & 1) == 0;
    #pragma unroll
    for (int m = 0; m < 2; m++) {
        int srcA = src_s[warp * 32 + m * 16 + gid];
        int srcB = src_s[warp * 32 + m * 16 + gid + 8];
        int msrc = even ? srcA : srcB;
        int colbase = 4 * (tig >> 1);
        #pragma unroll
        for (int nt = 0; nt < 8; nt++) {
            float c0 = c[m][nt][0], c1 = c[m][nt][1], c2 = c[m][nt][2], c3 = c[m][nt][3];
            float g0 = __shfl_xor_sync(0xffffffffu, c0, 1);
            float g1 = __shfl_xor_sync(0xffffffffu, c1, 1);
            float g2 = __shfl_xor_sync(0xffffffffu, c2, 1);
            float g3 = __shfl_xor_sync(0xffffffffu, c3, 1);
            float q0 = even ? c0 : g2;
            float q1 = even ? c1 : g3;
            float q2 = even ? g0 : c2;
            float q3 = even ? g1 : c3;
            if (msrc >= 0)
                red4(out + (size_t)msrc * 64 + nt * 8 + colbase, q0, q1, q2, q3);
        }
    }
}

extern "C" void kernel_launch(void* const* d_in, const int* in_sizes, int n_in,
                              void* d_out, int out_size) {
    const float* atom  = (const float*)d_in[0];
    const float* bondf = (const float*)d_in[1];
    const int*   pair  = (const int*)d_in[2];
    const float* K     = (const float*)d_in[3];
    const float* bias  = (const float*)d_in[4];
    float* out = (float*)d_out;

    int n_edges = in_sizes[2] / 2;

    cudaMemsetAsync(d_out, 0, (size_t)out_size * sizeof(float), 0);

    pack_w<<<(NBLK * 2048 + 255) / 256, 256>>>(K, bias);

    int grid = (n_edges + TM - 1) / TM;
    edge_main<<<grid, 128>>>(atom, bondf, pair, out, n_edges);
}

// round 4
// speedup vs baseline: 2.0267x; 1.0830x over previous
#include <cuda_runtime.h>
#include <cuda_fp16.h>
#include <cstdint>

#define TM      128
#define NBLK    17
#define WPITCH  72                 // uint32 pitch per k-pair row (conflict-free: bank = 8*tig+gid)
#define WBLK_U  (32 * WPITCH)      // 2304 uints = 9216 B per b-block
#define WBLK_V4 (WBLK_U / 4)       // 576 uint4 chunks

// W image in fp16x2, pre-laid-out exactly as the smem tile (pitch-72), so cp.async is a linear copy.
// Wp[b][p][n] = half2{ W(b, k=2p, n), W(b, k=2p+1, n) }, W(b,j,i) = K[b, i*64+j] (b<16) | bias[i*64+j]
__device__ uint4 W_img[NBLK * WBLK_V4];

static __device__ __forceinline__ void cp_async16(void* s, const void* g) {
    uint32_t sa = (uint32_t)__cvta_generic_to_shared(s);
    asm volatile("cp.async.cg.shared.global [%0], [%1], 16;" :: "r"(sa), "l"(g));
}
static __device__ __forceinline__ uint32_t h2u(__half2 h) {
    return *reinterpret_cast<uint32_t*>(&h);
}
static __device__ __forceinline__ __half2 u2h(uint32_t u) {
    return *reinterpret_cast<__half2*>(&u);
}
static __device__ __forceinline__ void mma16816(float* c, uint32_t a0, uint32_t a1,
                                                uint32_t a2, uint32_t a3,
                                                uint32_t b0, uint32_t b1) {
    asm volatile(
        "mma.sync.aligned.m16n8k16.row.col.f32.f16.f16.f32 "
        "{%0,%1,%2,%3}, {%4,%5,%6,%7}, {%8,%9}, {%0,%1,%2,%3};"
        : "+f"(c[0]), "+f"(c[1]), "+f"(c[2]), "+f"(c[3])
        : "r"(a0), "r"(a1), "r"(a2), "r"(a3), "r"(b0), "r"(b1));
}
static __device__ __forceinline__ void red4(float* p, float a, float b, float c, float d) {
    asm volatile("red.global.add.v4.f32 [%0], {%1, %2, %3, %4};"
                 :: "l"(p), "f"(a), "f"(b), "f"(c), "f"(d) : "memory");
}

__global__ void __launch_bounds__(256)
pack_w(const float* __restrict__ K, const float* __restrict__ bias) {
    int idx = blockIdx.x * blockDim.x + threadIdx.x;           // over 17*2048 half2 entries
    if (idx >= NBLK * 2048) return;
    int b = idx >> 11, r = idx & 2047;
    int p = r >> 6, n = r & 63;                                // k-pair p, col n
    int j0 = 2 * p, j1 = 2 * p + 1;
    float v0, v1;
    if (b < 16) { v0 = K[b * 4096 + n * 64 + j0]; v1 = K[b * 4096 + n * 64 + j1]; }
    else        { v0 = bias[n * 64 + j0];          v1 = bias[n * 64 + j1]; }
    __half2 h = __floats2half2_rn(v0, v1);
    ((uint32_t*)W_img)[b * WBLK_U + p * WPITCH + n] = h2u(h);
}

// GEMM-formulated edge network, fp16 m16n8k16, M=32 per warp, triple-buffered W,
// one barrier per b-block, 4 CTAs/SM.
__global__ void __launch_bounds__(128, 4)
edge_main(const float* __restrict__ atom, const float* __restrict__ bondf,
          const int* __restrict__ pair, float* __restrict__ out, int n_edges)
{
    __shared__ uint32_t Wp[3][WBLK_U];          // 27648 B
    __shared__ uint32_t bond_h[NBLK][TM];       // duplicated half2 of bond scale, 8704 B
    __shared__ int      src_s[TM];
    __shared__ int      nbr_s[TM];

    const int tid  = threadIdx.x;
    const int warp = tid >> 5, lane = tid & 31;
    const int gid  = lane >> 2, tig = lane & 3;
    const int e0   = blockIdx.x * TM;

    // Kick W_0, W_1 staging immediately (groups 0, 1).
    #pragma unroll
    for (int g = 0; g < 2; g++) {
        for (int i = tid; i < WBLK_V4; i += 128)
            cp_async16(&Wp[g][i * 4], &W_img[g * WBLK_V4 + i]);
        asm volatile("cp.async.commit_group;");
    }

    // Stage pair indices + bond tile (one thread per edge row), bond pre-converted to half2{s,s}.
    {
        int e = e0 + tid;
        int src = -1, nbr = 0;
        float4 q0 = {0,0,0,0}, q1 = q0, q2 = q0, q3 = q0;
        float one = 0.f;
        if (e < n_edges) {
            int2 pr = ((const int2*)pair)[e];
            src = pr.x; nbr = pr.y; one = 1.f;
            const float4* bp = (const float4*)(bondf + (size_t)e * 16);
            q0 = bp[0]; q1 = bp[1]; q2 = bp[2]; q3 = bp[3];
        }
        src_s[tid] = src; nbr_s[tid] = nbr;
        bond_h[0][tid]  = h2u(__float2half2_rn(q0.x));
        bond_h[1][tid]  = h2u(__float2half2_rn(q0.y));
        bond_h[2][tid]  = h2u(__float2half2_rn(q0.z));
        bond_h[3][tid]  = h2u(__float2half2_rn(q0.w));
        bond_h[4][tid]  = h2u(__float2half2_rn(q1.x));
        bond_h[5][tid]  = h2u(__float2half2_rn(q1.y));
        bond_h[6][tid]  = h2u(__float2half2_rn(q1.z));
        bond_h[7][tid]  = h2u(__float2half2_rn(q1.w));
        bond_h[8][tid]  = h2u(__float2half2_rn(q2.x));
        bond_h[9][tid]  = h2u(__float2half2_rn(q2.y));
        bond_h[10][tid] = h2u(__float2half2_rn(q2.z));
        bond_h[11][tid] = h2u(__float2half2_rn(q2.w));
        bond_h[12][tid] = h2u(__float2half2_rn(q3.x));
        bond_h[13][tid] = h2u(__float2half2_rn(q3.y));
        bond_h[14][tid] = h2u(__float2half2_rn(q3.z));
        bond_h[15][tid] = h2u(__float2half2_rn(q3.w));
        bond_h[16][tid] = h2u(__float2half2_rn(one));    // folded bias lane
    }

    // Neighbor features straight gmem -> half2 registers.
    // Rows owned: warp*32 + {gid, gid+8, gid+16, gid+24}.
    const int row0 = warp * 32 + gid;
    __half2 nb[4][8];
    #pragma unroll
    for (int r = 0; r < 4; r++) {
        int e = e0 + row0 + 8 * r;
        int nbr = 0;
        if (e < n_edges) nbr = ((const int2*)pair)[e].y;
        const float2* ap = (const float2*)(atom + (size_t)nbr * 64);
        #pragma unroll
        for (int q = 0; q < 8; q++) {
            float2 v = __ldg(ap + 4 * q + tig);
            nb[r][q] = __floats2half2_rn(v.x, v.y);
        }
    }

    float c[2][8][4];
    #pragma unroll
    for (int m = 0; m < 2; m++)
        #pragma unroll
        for (int nt = 0; nt < 8; nt++)
            c[m][nt][0] = c[m][nt][1] = c[m][nt][2] = c[m][nt][3] = 0.f;

    int wb = 0;   // buffer index b % 3
    for (int b = 0; b < NBLK; b++) {
        asm volatile("cp.async.wait_group 1;" ::: "memory");   // W_b resident
        __syncthreads();   // all warps: W_b visible AND done reading buf (b+2)%3 (last read at b-1)

        // Prefetch W_{b+2} into buf (b+2)%3 (not read or written by anything in flight).
        if (b + 2 < NBLK) {
            int dst = wb + 2 - ((wb + 2 >= 3) ? 3 : 0);
            for (int i = tid; i < WBLK_V4; i += 128)
                cp_async16(&Wp[dst][i * 4], &W_img[(b + 2) * WBLK_V4 + i]);
        }
        asm volatile("cp.async.commit_group;");   // one group per iteration keeps counts aligned

        __half2 bh[4];
        #pragma unroll
        for (int r = 0; r < 4; r++) bh[r] = u2h(bond_h[b][row0 + 8 * r]);

        const uint32_t* W = Wp[wb];
        #pragma unroll
        for (int s = 0; s < 4; s++) {
            uint32_t a00 = h2u(__hmul2(nb[0][2*s],   bh[0]));
            uint32_t a01 = h2u(__hmul2(nb[1][2*s],   bh[1]));
            uint32_t a02 = h2u(__hmul2(nb[0][2*s+1], bh[0]));
            uint32_t a03 = h2u(__hmul2(nb[1][2*s+1], bh[1]));
            uint32_t a10 = h2u(__hmul2(nb[2][2*s],   bh[2]));
            uint32_t a11 = h2u(__hmul2(nb[3][2*s],   bh[3]));
            uint32_t a12 = h2u(__hmul2(nb[2][2*s+1], bh[2]));
            uint32_t a13 = h2u(__hmul2(nb[3][2*s+1], bh[3]));
            #pragma unroll
            for (int nt = 0; nt < 8; nt++) {
                uint32_t b0 = W[(8*s + tig)     * WPITCH + nt*8 + gid];
                uint32_t b1 = W[(8*s + tig + 4) * WPITCH + nt*8 + gid];
                mma16816(c[0][nt], a00, a01, a02, a03, b0, b1);
                mma16816(c[1][nt], a10, a11, a12, a13, b0, b1);
            }
        }
        wb = (wb == 2) ? 0 : wb + 1;
    }

    // Epilogue: pair-shuffle to form 4-consecutive-col quads, then vectorized global RED.
    const bool even = (tig & 1) == 0;
    #pragma unroll
    for (int m = 0; m < 2; m++) {
        int srcA = src_s[warp * 32 + m * 16 + gid];
        int srcB = src_s[warp * 32 + m * 16 + gid + 8];
        int msrc = even ? srcA : srcB;
        int colbase = 4 * (tig >> 1);
        #pragma unroll
        for (int nt = 0; nt < 8; nt++) {
            float c0 = c[m][nt][0], c1 = c[m][nt][1], c2 = c[m][nt][2], c3 = c[m][nt][3];
            float g0 = __shfl_xor_sync(0xffffffffu, c0, 1);
            float g1 = __shfl_xor_sync(0xffffffffu, c1, 1);
            float g2 = __shfl_xor_sync(0xffffffffu, c2, 1);
            float g3 = __shfl_xor_sync(0xffffffffu, c3, 1);
            float q0 = even ? c0 : g2;
            float q1 = even ? c1 : g3;
            float q2 = even ? g0 : c2;
            float q3 = even ? g1 : c3;
            if (msrc >= 0)
                red4(out + (size_t)msrc * 64 + nt * 8 + colbase, q0, q1, q2, q3);
        }
    }
}

extern "C" void kernel_launch(void* const* d_in, const int* in_sizes, int n_in,
                              void* d_out, int out_size) {
    const float* atom  = (const float*)d_in[0];
    const float* bondf = (const float*)d_in[1];
    const int*   pair  = (const int*)d_in[2];
    const float* K     = (const float*)d_in[3];
    const float* bias  = (const float*)d_in[4];
    float* out = (float*)d_out;

    int n_edges = in_sizes[2] / 2;

    cudaMemsetAsync(d_out, 0, (size_t)out_size * sizeof(float), 0);

    pack_w<<<(NBLK * 2048 + 255) / 256, 256>>>(K, bias);

    int grid = (n_edges + TM - 1) / TM;
    edge_main<<<grid, 128>>>(atom, bondf, pair, out, n_edges);
}

// round 5
// speedup vs baseline: 2.0304x; 1.0018x over previous
#include <cuda_runtime.h>
#include <cuda_fp16.h>
#include <cstdint>

#define TM      256
#define NBLK    17
#define SLOTP   68                  // per-lane uint32 pitch (68%32=4 -> conflict-free LDS.128)
#define WBLK_U  (32 * SLOTP)        // 2176 uints = 8704 B per b-block
#define WBLK_V4 (WBLK_U / 4)        // 544 uint4
#define WALL_U  (NBLK * WBLK_U)     // 36992 uints = 147968 B
#define WALL_V4 (NBLK * WBLK_V4)    // 9248

// W packed per-thread-contiguous: for block b, lane L (gid=L>>2, tig=L&3), value v = s*16+nt*2+h:
//   half2{ W(b, j=2p, n), W(b, j=2p+1, n) },  p = 8s + tig + 4h,  n = nt*8 + gid
//   where W(b, j, i) = K[b, i*64 + j] (b<16) or bias[i*64 + j] (b=16).
__device__ uint4 W_img[WALL_V4];

static __device__ __forceinline__ void cp_async16(void* s, const void* g) {
    uint32_t sa = (uint32_t)__cvta_generic_to_shared(s);
    asm volatile("cp.async.cg.shared.global [%0], [%1], 16;" :: "r"(sa), "l"(g));
}
static __device__ __forceinline__ uint32_t h2u(__half2 h) {
    return *reinterpret_cast<uint32_t*>(&h);
}
static __device__ __forceinline__ __half2 u2h(uint32_t u) {
    return *reinterpret_cast<__half2*>(&u);
}
static __device__ __forceinline__ void mma16816(float* c, uint32_t a0, uint32_t a1,
                                                uint32_t a2, uint32_t a3,
                                                uint32_t b0, uint32_t b1) {
    asm volatile(
        "mma.sync.aligned.m16n8k16.row.col.f32.f16.f16.f32 "
        "{%0,%1,%2,%3}, {%4,%5,%6,%7}, {%8,%9}, {%0,%1,%2,%3};"
        : "+f"(c[0]), "+f"(c[1]), "+f"(c[2]), "+f"(c[3])
        : "r"(a0), "r"(a1), "r"(a2), "r"(a3), "r"(b0), "r"(b1));
}
static __device__ __forceinline__ void red4(float* p, float a, float b, float c, float d) {
    asm volatile("red.global.add.v4.f32 [%0], {%1, %2, %3, %4};"
                 :: "l"(p), "f"(a), "f"(b), "f"(c), "f"(d) : "memory");
}

// Fused: zero the output AND pack W (one launch). 3125 blocks x 256 = 800000 threads
// = exactly out_size/4 float4 stores; first 34816 threads also pack one half2.
__global__ void __launch_bounds__(256)
zero_pack(const float* __restrict__ K, const float* __restrict__ bias,
          float4* __restrict__ out4, int n_out4) {
    int idx = blockIdx.x * blockDim.x + threadIdx.x;
    if (idx < n_out4) out4[idx] = make_float4(0.f, 0.f, 0.f, 0.f);
    if (idx < NBLK * 2048) {
        int b = idx >> 11, r = idx & 2047;
        int slot = r >> 6, v = r & 63;
        int gid = slot >> 2, tig = slot & 3;
        int s = v >> 4, r2 = v & 15, nt = r2 >> 1, h = r2 & 1;
        int p = 8 * s + tig + 4 * h;
        int n = nt * 8 + gid;
        float v0, v1;
        if (b < 16) { v0 = K[b * 4096 + n * 64 + 2 * p]; v1 = K[b * 4096 + n * 64 + 2 * p + 1]; }
        else        { v0 = bias[n * 64 + 2 * p];          v1 = bias[n * 64 + 2 * p + 1]; }
        ((uint32_t*)W_img)[b * WBLK_U + slot * SLOTP + v] = h2u(__floats2half2_rn(v0, v1));
    }
}

// All-of-W-resident fp16 MMA edge kernel: zero mainloop barriers.
__global__ void __launch_bounds__(256, 1)
edge_main(const float* __restrict__ atom, const float* __restrict__ bondf,
          const int* __restrict__ pair, float* __restrict__ out, int n_edges)
{
    extern __shared__ uint32_t smw[];
    uint32_t* Wall   = smw;                     // 36992 uints (147968 B)
    uint32_t* bond_h = smw + WALL_U;            // [NBLK][TM] dup-half2  (17408 B)
    int*      src_s  = (int*)(bond_h + NBLK * TM);  // [TM]

    const int tid  = threadIdx.x;
    const int warp = tid >> 5, lane = tid & 31;
    const int gid  = lane >> 2, tig = lane & 3;
    const int e0   = blockIdx.x * TM;

    // Kick the whole W image in 3 groups: blocks [0,2) [2,6) [6,17).
    {
        uint4* Wd = (uint4*)Wall;
        for (int i = tid; i < 2 * WBLK_V4; i += 256) cp_async16(Wd + i, W_img + i);
        asm volatile("cp.async.commit_group;");
        for (int i = tid; i < 4 * WBLK_V4; i += 256)
            cp_async16(Wd + 2 * WBLK_V4 + i, W_img + 2 * WBLK_V4 + i);
        asm volatile("cp.async.commit_group;");
        for (int i = tid; i < 11 * WBLK_V4; i += 256)
            cp_async16(Wd + 6 * WBLK_V4 + i, W_img + 6 * WBLK_V4 + i);
        asm volatile("cp.async.commit_group;");
    }

    // Stage bond (dup half2) + src for row tid.
    {
        int e = e0 + tid;
        int src = -1;
        float4 q0 = {0,0,0,0}, q1 = q0, q2 = q0, q3 = q0;
        float one = 0.f;
        if (e < n_edges) {
            src = ((const int2*)pair)[e].x;
            one = 1.f;
            const float4* bp = (const float4*)(bondf + (size_t)e * 16);
            q0 = bp[0]; q1 = bp[1]; q2 = bp[2]; q3 = bp[3];
        }
        src_s[tid] = src;
        bond_h[0*TM+tid]  = h2u(__float2half2_rn(q0.x));
        bond_h[1*TM+tid]  = h2u(__float2half2_rn(q0.y));
        bond_h[2*TM+tid]  = h2u(__float2half2_rn(q0.z));
        bond_h[3*TM+tid]  = h2u(__float2half2_rn(q0.w));
        bond_h[4*TM+tid]  = h2u(__float2half2_rn(q1.x));
        bond_h[5*TM+tid]  = h2u(__float2half2_rn(q1.y));
        bond_h[6*TM+tid]  = h2u(__float2half2_rn(q1.z));
        bond_h[7*TM+tid]  = h2u(__float2half2_rn(q1.w));
        bond_h[8*TM+tid]  = h2u(__float2half2_rn(q2.x));
        bond_h[9*TM+tid]  = h2u(__float2half2_rn(q2.y));
        bond_h[10*TM+tid] = h2u(__float2half2_rn(q2.z));
        bond_h[11*TM+tid] = h2u(__float2half2_rn(q2.w));
        bond_h[12*TM+tid] = h2u(__float2half2_rn(q3.x));
        bond_h[13*TM+tid] = h2u(__float2half2_rn(q3.y));
        bond_h[14*TM+tid] = h2u(__float2half2_rn(q3.z));
        bond_h[15*TM+tid] = h2u(__float2half2_rn(q3.w));
        bond_h[16*TM+tid] = h2u(__float2half2_rn(one));
    }

    // Neighbor features gmem -> half2 regs. Rows: warp*32 + gid + 8r.
    const int row0 = warp * 32 + gid;
    __half2 nb[4][8];
    #pragma unroll
    for (int r = 0; r < 4; r++) {
        int e = e0 + row0 + 8 * r;
        int nbr = (e < n_edges) ? ((const int2*)pair)[e].y : 0;
        const float2* ap = (const float2*)(atom + (size_t)nbr * 64);
        #pragma unroll
        for (int q = 0; q < 8; q++) {
            float2 v = __ldg(ap + 4 * q + tig);
            nb[r][q] = __floats2half2_rn(v.x, v.y);
        }
    }

    float c[2][8][4];
    #pragma unroll
    for (int m = 0; m < 2; m++)
        #pragma unroll
        for (int nt = 0; nt < 8; nt++)
            c[m][nt][0] = c[m][nt][1] = c[m][nt][2] = c[m][nt][3] = 0.f;

    #pragma unroll 1
    for (int b = 0; b < NBLK; b++) {
        if (b == 0) { asm volatile("cp.async.wait_group 2;" ::: "memory"); __syncthreads(); }
        else if (b == 2) { asm volatile("cp.async.wait_group 1;" ::: "memory"); __syncthreads(); }
        else if (b == 6) { asm volatile("cp.async.wait_group 0;" ::: "memory"); __syncthreads(); }

        const uint32_t* wbase = Wall + b * WBLK_U + lane * SLOTP;
        __half2 bh0 = u2h(bond_h[b * TM + row0]);
        __half2 bh1 = u2h(bond_h[b * TM + row0 + 8]);
        __half2 bh2 = u2h(bond_h[b * TM + row0 + 16]);
        __half2 bh3 = u2h(bond_h[b * TM + row0 + 24]);

        #pragma unroll
        for (int s = 0; s < 4; s++) {
            uint4 q0 = *(const uint4*)(wbase + s * 16);
            uint4 q1 = *(const uint4*)(wbase + s * 16 + 4);
            uint4 q2 = *(const uint4*)(wbase + s * 16 + 8);
            uint4 q3 = *(const uint4*)(wbase + s * 16 + 12);

            uint32_t a00 = h2u(__hmul2(nb[0][2*s],   bh0));
            uint32_t a01 = h2u(__hmul2(nb[1][2*s],   bh1));
            uint32_t a02 = h2u(__hmul2(nb[0][2*s+1], bh0));
            uint32_t a03 = h2u(__hmul2(nb[1][2*s+1], bh1));
            uint32_t a10 = h2u(__hmul2(nb[2][2*s],   bh2));
            uint32_t a11 = h2u(__hmul2(nb[3][2*s],   bh3));
            uint32_t a12 = h2u(__hmul2(nb[2][2*s+1], bh2));
            uint32_t a13 = h2u(__hmul2(nb[3][2*s+1], bh3));

            mma16816(c[0][0], a00, a01, a02, a03, q0.x, q0.y);
            mma16816(c[1][0], a10, a11, a12, a13, q0.x, q0.y);
            mma16816(c[0][1], a00, a01, a02, a03, q0.z, q0.w);
            mma16816(c[1][1], a10, a11, a12, a13, q0.z, q0.w);
            mma16816(c[0][2], a00, a01, a02, a03, q1.x, q1.y);
            mma16816(c[1][2], a10, a11, a12, a13, q1.x, q1.y);
            mma16816(c[0][3], a00, a01, a02, a03, q1.z, q1.w);
            mma16816(c[1][3], a10, a11, a12, a13, q1.z, q1.w);
            mma16816(c[0][4], a00, a01, a02, a03, q2.x, q2.y);
            mma16816(c[1][4], a10, a11, a12, a13, q2.x, q2.y);
            mma16816(c[0][5], a00, a01, a02, a03, q2.z, q2.w);
            mma16816(c[1][5], a10, a11, a12, a13, q2.z, q2.w);
            mma16816(c[0][6], a00, a01, a02, a03, q3.x, q3.y);
            mma16816(c[1][6], a10, a11, a12, a13, q3.x, q3.y);
            mma16816(c[0][7], a00, a01, a02, a03, q3.z, q3.w);
            mma16816(c[1][7], a10, a11, a12, a13, q3.z, q3.w);
        }
    }

    // Epilogue: pair-shuffle into 4-col quads, vectorized global RED.
    const bool even = (tig & 1) == 0;
    #pragma unroll
    for (int m = 0; m < 2; m++) {
        int srcA = src_s[warp * 32 + m * 16 + gid];
        int srcB = src_s[warp * 32 + m * 16 + gid + 8];
        int msrc = even ? srcA : srcB;
        int colbase = 4 * (tig >> 1);
        #pragma unroll
        for (int nt = 0; nt < 8; nt++) {
            float c0 = c[m][nt][0], c1 = c[m][nt][1], c2 = c[m][nt][2], c3 = c[m][nt][3];
            float g0 = __shfl_xor_sync(0xffffffffu, c0, 1);
            float g1 = __shfl_xor_sync(0xffffffffu, c1, 1);
            float g2 = __shfl_xor_sync(0xffffffffu, c2, 1);
            float g3 = __shfl_xor_sync(0xffffffffu, c3, 1);
            float q0 = even ? c0 : g2;
            float q1 = even ? c1 : g3;
            float q2 = even ? g0 : c2;
            float q3 = even ? g1 : c3;
            if (msrc >= 0)
                red4(out + (size_t)msrc * 64 + nt * 8 + colbase, q0, q1, q2, q3);
        }
    }
}

extern "C" void kernel_launch(void* const* d_in, const int* in_sizes, int n_in,
                              void* d_out, int out_size) {
    const float* atom  = (const float*)d_in[0];
    const float* bondf = (const float*)d_in[1];
    const int*   pair  = (const int*)d_in[2];
    const float* K     = (const float*)d_in[3];
    const float* bias  = (const float*)d_in[4];
    float* out = (float*)d_out;

    int n_edges = in_sizes[2] / 2;
    int n_out4  = out_size / 4;

    zero_pack<<<(n_out4 + 255) / 256, 256>>>(K, bias, (float4*)out, n_out4);

    int smem_bytes = (WALL_U + NBLK * TM) * (int)sizeof(uint32_t) + TM * (int)sizeof(int);
    cudaFuncSetAttribute(edge_main, cudaFuncAttributeMaxDynamicSharedMemorySize, smem_bytes);

    int grid = (n_edges + TM - 1) / TM;
    edge_main<<<grid, 256, smem_bytes>>>(atom, bondf, pair, out, n_edges);
}

// round 7
// speedup vs baseline: 2.5644x; 1.2630x over previous
#include <cuda_runtime.h>
#include <cuda_fp16.h>
#include <cstdint>

#define TM      256
#define NBLK    17
// ---- fallback (mma.sync) W layout: per-lane-contiguous, pitch 68 ----
#define SLOTP   68
#define WBLK_U  (32 * SLOTP)        // 2176 uints per block
#define WBLK_V4 (WBLK_U / 4)        // 544
// ---- tcgen05 W layout: SW128 blocked-atom f16 image, 8 KB per block ----
#define TCBLK_U  2048
#define TCBLK_V4 512

__device__ uint4 W_img[NBLK * WBLK_V4];   // fallback image
__device__ uint4 W_tc [NBLK * TCBLK_V4];  // tcgen05 image

// ---------------- shared helpers ----------------
static __device__ __forceinline__ void cp_async16(uint32_t s, const void* g) {
    asm volatile("cp.async.cg.shared.global [%0], [%1], 16;" :: "r"(s), "l"(g));
}
static __device__ __forceinline__ uint32_t smem_u32(const void* p) {
    uint32_t a;
    asm("{ .reg .u64 t; cvta.to.shared.u64 t, %1; cvt.u32.u64 %0, t; }" : "=r"(a) : "l"(p));
    return a;
}
static __device__ __forceinline__ uint32_t h2u(__half2 h) {
    return *reinterpret_cast<uint32_t*>(&h);
}
static __device__ __forceinline__ __half2 u2h(uint32_t u) {
    return *reinterpret_cast<__half2*>(&u);
}
static __device__ __forceinline__ void red4(float* p, float a, float b, float c, float d) {
    asm volatile("red.global.add.v4.f32 [%0], {%1, %2, %3, %4};"
                 :: "l"(p), "f"(a), "f"(b), "f"(c), "f"(d) : "memory");
}
static __device__ __forceinline__ void mma16816(float* c, uint32_t a0, uint32_t a1,
                                                uint32_t a2, uint32_t a3,
                                                uint32_t b0, uint32_t b1) {
    asm volatile(
        "mma.sync.aligned.m16n8k16.row.col.f32.f16.f16.f32 "
        "{%0,%1,%2,%3}, {%4,%5,%6,%7}, {%8,%9}, {%0,%1,%2,%3};"
        : "+f"(c[0]), "+f"(c[1]), "+f"(c[2]), "+f"(c[3])
        : "r"(a0), "r"(a1), "r"(a2), "r"(a3), "r"(b0), "r"(b1));
}

// ---------------- tcgen05 helpers (only referenced under the feature guard) ----------------
#if defined(__CUDA_ARCH__) && defined(__CUDA_ARCH_FEAT_SM103_ALL)
#define TC_IDESC ((1u << 4) | (8u << 17) | (8u << 24))   // kind::f16: fp16 in, f32 acc, M=128, N=64
#define DBASE ((2ull << 61) | (1ull << 46) | (64ull << 32) | (1ull << 16))  // SW128, v1, SBO=64, LBO=1

static __device__ __forceinline__ bool elect1() {
    uint32_t p;
    asm volatile("{ .reg .pred P; elect.sync _|P, 0xFFFFFFFF; selp.b32 %0, 1, 0, P; }" : "=r"(p));
    return p != 0;
}
static __device__ __forceinline__ void mbar_init(uint32_t a, uint32_t c) {
    asm volatile("mbarrier.init.shared.b64 [%0], %1;" :: "r"(a), "r"(c) : "memory");
}
static __device__ __forceinline__ void mbar_wait(uint32_t a, uint32_t ph) {
    asm volatile(
        "{ .reg .pred P;\n"
        "LW_%=:\n"
        "mbarrier.try_wait.parity.acquire.cta.shared::cta.b64 P, [%0], %1, 0x989680;\n"
        "@!P bra LW_%=;\n"
        "}" :: "r"(a), "r"(ph) : "memory");
}
static __device__ __forceinline__ void tc_mma_f16(uint32_t d, uint32_t a, uint64_t bd,
                                                  uint32_t en) {
    asm volatile(
        "{ .reg .pred p; setp.ne.u32 p, %5, 0;\n"
        "tcgen05.mma.cta_group::1.kind::f16 [%0], [%1], %2, %3, {%4, %4, %4, %4}, p;\n"
        "}"
        :: "r"(d), "r"(a), "l"(bd), "r"(TC_IDESC), "r"(0u), "r"(en) : "memory");
}
static __device__ __forceinline__ void tmem_st32(uint32_t addr, const uint32_t* r) {
    asm volatile(
        "tcgen05.st.sync.aligned.32x32b.x32.b32 [%0], "
        "{%1,%2,%3,%4,%5,%6,%7,%8,%9,%10,%11,%12,%13,%14,%15,%16,"
        "%17,%18,%19,%20,%21,%22,%23,%24,%25,%26,%27,%28,%29,%30,%31,%32};"
        :: "r"(addr),
           "r"(r[0]),  "r"(r[1]),  "r"(r[2]),  "r"(r[3]),
           "r"(r[4]),  "r"(r[5]),  "r"(r[6]),  "r"(r[7]),
           "r"(r[8]),  "r"(r[9]),  "r"(r[10]), "r"(r[11]),
           "r"(r[12]), "r"(r[13]), "r"(r[14]), "r"(r[15]),
           "r"(r[16]), "r"(r[17]), "r"(r[18]), "r"(r[19]),
           "r"(r[20]), "r"(r[21]), "r"(r[22]), "r"(r[23]),
           "r"(r[24]), "r"(r[25]), "r"(r[26]), "r"(r[27]),
           "r"(r[28]), "r"(r[29]), "r"(r[30]), "r"(r[31])
        : "memory");
}
static __device__ __forceinline__ void tmem_ld32(uint32_t* r, uint32_t addr) {
    asm volatile(
        "tcgen05.ld.sync.aligned.32x32b.x32.b32 "
        "{%0,%1,%2,%3,%4,%5,%6,%7,%8,%9,%10,%11,%12,%13,%14,%15,"
        "%16,%17,%18,%19,%20,%21,%22,%23,%24,%25,%26,%27,%28,%29,%30,%31}, [%32];"
        : "=r"(r[0]),  "=r"(r[1]),  "=r"(r[2]),  "=r"(r[3]),
          "=r"(r[4]),  "=r"(r[5]),  "=r"(r[6]),  "=r"(r[7]),
          "=r"(r[8]),  "=r"(r[9]),  "=r"(r[10]), "=r"(r[11]),
          "=r"(r[12]), "=r"(r[13]), "=r"(r[14]), "=r"(r[15]),
          "=r"(r[16]), "=r"(r[17]), "=r"(r[18]), "=r"(r[19]),
          "=r"(r[20]), "=r"(r[21]), "=r"(r[22]), "=r"(r[23]),
          "=r"(r[24]), "=r"(r[25]), "=r"(r[26]), "=r"(r[27]),
          "=r"(r[28]), "=r"(r[29]), "=r"(r[30]), "=r"(r[31])
        : "r"(addr));
}
#endif

// ---------------- zero output + pack both W images ----------------
__global__ void __launch_bounds__(256)
zero_pack(const float* __restrict__ K, const float* __restrict__ bias,
          float4* __restrict__ out4, int n_out4) {
    int idx = blockIdx.x * blockDim.x + threadIdx.x;
    if (idx < n_out4) out4[idx] = make_float4(0.f, 0.f, 0.f, 0.f);
    if (idx < NBLK * 2048) {
        int b = idx >> 11, r = idx & 2047;
        // fallback image: per-lane-contiguous values
        {
            int slot = r >> 6, v = r & 63;
            int gid = slot >> 2, tig = slot & 3;
            int s = v >> 4, r2 = v & 15, nt = r2 >> 1, h = r2 & 1;
            int p = 8 * s + tig + 4 * h;
            int n = nt * 8 + gid;
            float v0, v1;
            if (b < 16) { v0 = K[b * 4096 + n * 64 + 2 * p]; v1 = K[b * 4096 + n * 64 + 2 * p + 1]; }
            else        { v0 = bias[n * 64 + 2 * p];          v1 = bias[n * 64 + 2 * p + 1]; }
            ((uint32_t*)W_img)[b * WBLK_U + slot * SLOTP + v] = h2u(__floats2half2_rn(v0, v1));
        }
        // tcgen05 image: B[n][k] f16, SW128 atoms (8 rows x 128 B), K=64 f16 = one atom column
        {
            int n = r >> 5, p = r & 31;
            float v0, v1;
            if (b < 16) { v0 = K[b * 4096 + n * 64 + 2 * p]; v1 = K[b * 4096 + n * 64 + 2 * p + 1]; }
            else        { v0 = bias[n * 64 + 2 * p];          v1 = bias[n * 64 + 2 * p + 1]; }
            int byte = (n >> 3) * 1024 + (n & 7) * 128 + p * 4;
            int sw = byte ^ ((byte >> 3) & 0x70);
            ((uint32_t*)W_tc)[b * TCBLK_U + (sw >> 2)] = h2u(__floats2half2_rn(v0, v1));
        }
    }
}

__global__ void __launch_bounds__(256)
edge_main(const float* __restrict__ atom, const float* __restrict__ bondf,
          const int* __restrict__ pair, float* __restrict__ out, int n_edges)
{
    const int tid  = threadIdx.x;
    const int warp = tid >> 5;
    const int e0   = blockIdx.x * TM;

#if defined(__CUDA_ARCH__) && defined(__CUDA_ARCH_FEAT_SM103_ALL)
    // ================= tcgen05 path (sm_103a cubin) =================
    __shared__ __align__(1024) uint32_t Wsm[2][TCBLK_U];   // 16384 B, 1024-aligned for SW128
    __shared__ uint32_t bond_h[NBLK * TM];                 // 17408 B
    __shared__ int      src_s[TM];                         // 1024 B
    __shared__ __align__(16) uint32_t hdr[4];              // [0] tmem ptr | [2..3] mbarrier

    const uint32_t TP = smem_u32(&hdr[0]);
    const uint32_t MB = smem_u32(&hdr[2]);

    const int sub = tid >> 7;          // M-subtile (two 128-row tiles per CTA)
    const int row = tid & 127;
    const int e   = e0 + tid;

    // Alloc THEN relinquish, both on warp 0, sequential in program order.
    // (Relinquish racing ahead of the alloc on another warp makes the alloc illegal.)
    if (warp == 0) {
        asm volatile("tcgen05.alloc.cta_group::1.sync.aligned.shared::cta.b32 [%0], %1;"
                     :: "r"(TP), "r"(256u) : "memory");
        asm volatile("tcgen05.relinquish_alloc_permit.cta_group::1.sync.aligned;");
    }
    if (tid == 0) mbar_init(MB, 1);

    // Stage W_0.
    for (int i = tid; i < TCBLK_V4; i += 256)
        cp_async16(smem_u32(&Wsm[0][0]) + i * 16, W_tc + i);
    asm volatile("cp.async.commit_group;");

    // Stage bond (dup half2) + src; gather neighbor row -> 32 half2 regs.
    int src = -1, nbr = 0;
    {
        float4 q0 = {0,0,0,0}, q1 = q0, q2 = q0, q3 = q0;
        float one = 0.f;
        if (e < n_edges) {
            int2 pr = ((const int2*)pair)[e];
            src = pr.x; nbr = pr.y; one = 1.f;
            const float4* bp = (const float4*)(bondf + (size_t)e * 16);
            q0 = bp[0]; q1 = bp[1]; q2 = bp[2]; q3 = bp[3];
        }
        src_s[tid] = src;
        const float bv[16] = {q0.x,q0.y,q0.z,q0.w, q1.x,q1.y,q1.z,q1.w,
                              q2.x,q2.y,q2.z,q2.w, q3.x,q3.y,q3.z,q3.w};
        #pragma unroll
        for (int b = 0; b < 16; b++) bond_h[b * TM + tid] = h2u(__float2half2_rn(bv[b]));
        bond_h[16 * TM + tid] = h2u(__float2half2_rn(one));
    }
    __half2 nb[32];
    {
        const float4* ap = (const float4*)(atom + (size_t)nbr * 64);
        #pragma unroll
        for (int q = 0; q < 16; q++) {
            float4 v = __ldg(ap + q);
            nb[2 * q]     = __floats2half2_rn(v.x, v.y);
            nb[2 * q + 1] = __floats2half2_rn(v.z, v.w);
        }
    }
    __syncthreads();   // alloc result, mbar init, bond, src all visible

    uint32_t tmem;
    asm volatile("ld.shared.b32 %0, [%1];" : "=r"(tmem) : "r"(TP));
    const uint32_t Dt = tmem;                 // D: sub0 cols 0..63, sub1 cols 64..127
    const uint32_t At = tmem + 128;           // A: sub0 cols 128..159, sub1 160..191
    const uint32_t lane_off = (uint32_t)(row >> 5) << 21;   // == (warp%4) lane group
    const uint32_t myA = At + (uint32_t)sub * 32 + lane_off;

    for (int b = 0; b < NBLK; b++) {
        if (b > 0) {
            mbar_wait(MB, (b - 1) & 1);       // MMA_{b-1} complete: A + W[(b+1)&1] reusable
            asm volatile("tcgen05.fence::after_thread_sync;" ::: "memory");
        }
        // Build Z_b in TMEM.
        {
            __half2 bh = u2h(bond_h[b * TM + tid]);
            uint32_t z[32];
            #pragma unroll
            for (int j = 0; j < 32; j++) z[j] = h2u(__hmul2(nb[j], bh));
            tmem_st32(myA, z);
        }
        asm volatile("tcgen05.wait::st.sync.aligned;" ::: "memory");
        asm volatile("tcgen05.fence::before_thread_sync;" ::: "memory");
        // Stage W_{b+1}.
        if (b + 1 < NBLK) {
            uint32_t dst = smem_u32(&Wsm[(b + 1) & 1][0]);
            for (int i = tid; i < TCBLK_V4; i += 256)
                cp_async16(dst + i * 16, W_tc + (b + 1) * TCBLK_V4 + i);
        }
        asm volatile("cp.async.commit_group;");
        asm volatile("cp.async.wait_group 1;" ::: "memory");   // W_b resident
        asm volatile("fence.proxy.async.shared::cta;" ::: "memory");
        __syncthreads();

        if (warp == 0) {
            asm volatile("tcgen05.fence::after_thread_sync;" ::: "memory");
            if (elect1()) {
                uint64_t bd = DBASE | (uint64_t)((smem_u32(&Wsm[b & 1][0]) >> 4) & 0x3FFF);
                #pragma unroll
                for (int k = 0; k < 4; k++) {
                    uint32_t en = (b > 0 || k > 0) ? 1u : 0u;
                    tc_mma_f16(Dt,      At      + k * 8, bd + k * 2, en);
                    tc_mma_f16(Dt + 64, At + 32 + k * 8, bd + k * 2, en);
                }
                asm volatile(
                    "tcgen05.commit.cta_group::1.mbarrier::arrive::one.shared::cluster.b64 [%0];"
                    :: "r"(MB) : "memory");
            }
        }
    }
    mbar_wait(MB, (NBLK - 1) & 1);            // completion 16, parity 0 (sequential chain)
    asm volatile("tcgen05.fence::after_thread_sync;" ::: "memory");

    // Readout + segment-sum RED.
    {
        uint32_t d0[32], d1[32];
        tmem_ld32(d0, Dt + (uint32_t)sub * 64 + lane_off);
        tmem_ld32(d1, Dt + (uint32_t)sub * 64 + 32 + lane_off);
        asm volatile("tcgen05.wait::ld.sync.aligned;" ::: "memory");
        if (src >= 0) {
            float* op = out + (size_t)src * 64;
            #pragma unroll
            for (int q = 0; q < 8; q++)
                red4(op + 4 * q, __uint_as_float(d0[4*q]),   __uint_as_float(d0[4*q+1]),
                                 __uint_as_float(d0[4*q+2]), __uint_as_float(d0[4*q+3]));
            #pragma unroll
            for (int q = 0; q < 8; q++)
                red4(op + 32 + 4 * q, __uint_as_float(d1[4*q]),   __uint_as_float(d1[4*q+1]),
                                      __uint_as_float(d1[4*q+2]), __uint_as_float(d1[4*q+3]));
        }
    }
    __syncthreads();
    if (warp == 0)
        asm volatile("tcgen05.dealloc.cta_group::1.sync.aligned.b32 %0, %1;"
                     :: "r"(tmem), "r"(256u));
#else
    // ================= fallback: mma.sync fp16 (compute_103 cubin) =================
    __shared__ uint32_t Wall[3 * WBLK_U];       // 26112 B
    __shared__ uint32_t bond_h[NBLK * TM];      // 17408 B
    __shared__ int      src_s[TM];              // 1024 B

    const int lane = tid & 31;
    const int gid  = lane >> 2, tig = lane & 3;

    // Stage W_0, W_1 (groups 0, 1).
    #pragma unroll
    for (int g = 0; g < 2; g++) {
        for (int i = tid; i < WBLK_V4; i += 256)
            cp_async16(smem_u32(Wall) + (g * WBLK_V4 + i) * 16, W_img + g * WBLK_V4 + i);
        asm volatile("cp.async.commit_group;");
    }

    // Stage bond + src.
    {
        int e = e0 + tid;
        int src = -1;
        float4 q0 = {0,0,0,0}, q1 = q0, q2 = q0, q3 = q0;
        float one = 0.f;
        if (e < n_edges) {
            src = ((const int2*)pair)[e].x;
            one = 1.f;
            const float4* bp = (const float4*)(bondf + (size_t)e * 16);
            q0 = bp[0]; q1 = bp[1]; q2 = bp[2]; q3 = bp[3];
        }
        src_s[tid] = src;
        const float bv[16] = {q0.x,q0.y,q0.z,q0.w, q1.x,q1.y,q1.z,q1.w,
                              q2.x,q2.y,q2.z,q2.w, q3.x,q3.y,q3.z,q3.w};
        #pragma unroll
        for (int b = 0; b < 16; b++) bond_h[b * TM + tid] = h2u(__float2half2_rn(bv[b]));
        bond_h[16 * TM + tid] = h2u(__float2half2_rn(one));
    }

    // Neighbor features gmem -> half2 regs. Rows: warp*32 + gid + 8r.
    const int row0 = warp * 32 + gid;
    __half2 nb[4][8];
    #pragma unroll
    for (int r = 0; r < 4; r++) {
        int e = e0 + row0 + 8 * r;
        int nbr = (e < n_edges) ? ((const int2*)pair)[e].y : 0;
        const float2* ap = (const float2*)(atom + (size_t)nbr * 64);
        #pragma unroll
        for (int q = 0; q < 8; q++) {
            float2 v = __ldg(ap + 4 * q + tig);
            nb[r][q] = __floats2half2_rn(v.x, v.y);
        }
    }

    float c[2][8][4];
    #pragma unroll
    for (int m = 0; m < 2; m++)
        #pragma unroll
        for (int nt = 0; nt < 8; nt++)
            c[m][nt][0] = c[m][nt][1] = c[m][nt][2] = c[m][nt][3] = 0.f;

    int wb = 0;   // b % 3
    for (int b = 0; b < NBLK; b++) {
        asm volatile("cp.async.wait_group 1;" ::: "memory");   // W_b resident
        __syncthreads();   // W_b visible; buf (b+2)%3 free (last read at b-1)

        if (b + 2 < NBLK) {
            int dst = wb + 2 - ((wb + 2 >= 3) ? 3 : 0);
            for (int i = tid; i < WBLK_V4; i += 256)
                cp_async16(smem_u32(Wall) + (dst * WBLK_V4 + i) * 16,
                           W_img + (b + 2) * WBLK_V4 + i);
        }
        asm volatile("cp.async.commit_group;");

        __half2 bh0 = u2h(bond_h[b * TM + row0]);
        __half2 bh1 = u2h(bond_h[b * TM + row0 + 8]);
        __half2 bh2 = u2h(bond_h[b * TM + row0 + 16]);
        __half2 bh3 = u2h(bond_h[b * TM + row0 + 24]);

        const uint32_t* wbase = Wall + wb * WBLK_U + lane * SLOTP;
        #pragma unroll
        for (int s = 0; s < 4; s++) {
            uint4 q0 = *(const uint4*)(wbase + s * 16);
            uint4 q1 = *(const uint4*)(wbase + s * 16 + 4);
            uint4 q2 = *(const uint4*)(wbase + s * 16 + 8);
            uint4 q3 = *(const uint4*)(wbase + s * 16 + 12);

            uint32_t a00 = h2u(__hmul2(nb[0][2*s],   bh0));
            uint32_t a01 = h2u(__hmul2(nb[1][2*s],   bh1));
            uint32_t a02 = h2u(__hmul2(nb[0][2*s+1], bh0));
            uint32_t a03 = h2u(__hmul2(nb[1][2*s+1], bh1));
            uint32_t a10 = h2u(__hmul2(nb[2][2*s],   bh2));
            uint32_t a11 = h2u(__hmul2(nb[3][2*s],   bh3));
            uint32_t a12 = h2u(__hmul2(nb[2][2*s+1], bh2));
            uint32_t a13 = h2u(__hmul2(nb[3][2*s+1], bh3));

            mma16816(c[0][0], a00, a01, a02, a03, q0.x, q0.y);
            mma16816(c[1][0], a10, a11, a12, a13, q0.x, q0.y);
            mma16816(c[0][1], a00, a01, a02, a03, q0.z, q0.w);
            mma16816(c[1][1], a10, a11, a12, a13, q0.z, q0.w);
            mma16816(c[0][2], a00, a01, a02, a03, q1.x, q1.y);
            mma16816(c[1][2], a10, a11, a12, a13, q1.x, q1.y);
            mma16816(c[0][3], a00, a01, a02, a03, q1.z, q1.w);
            mma16816(c[1][3], a10, a11, a12, a13, q1.z, q1.w);
            mma16816(c[0][4], a00, a01, a02, a03, q2.x, q2.y);
            mma16816(c[1][4], a10, a11, a12, a13, q2.x, q2.y);
            mma16816(c[0][5], a00, a01, a02, a03, q2.z, q2.w);
            mma16816(c[1][5], a10, a11, a12, a13, q2.z, q2.w);
            mma16816(c[0][6], a00, a01, a02, a03, q3.x, q3.y);
            mma16816(c[1][6], a10, a11, a12, a13, q3.x, q3.y);
            mma16816(c[0][7], a00, a01, a02, a03, q3.z, q3.w);
            mma16816(c[1][7], a10, a11, a12, a13, q3.z, q3.w);
        }
        wb = (wb == 2) ? 0 : wb + 1;
    }

    // Epilogue: pair-shuffle into 4-col quads, vectorized global RED.
    const bool even = (tig & 1) == 0;
    #pragma unroll
    for (int m = 0; m < 2; m++) {
        int srcA = src_s[warp * 32 + m * 16 + gid];
        int srcB = src_s[warp * 32 + m * 16 + gid + 8];
        int msrc = even ? srcA : srcB;
        int colbase = 4 * (tig >> 1);
        #pragma unroll
        for (int nt = 0; nt < 8; nt++) {
            float c0 = c[m][nt][0], c1 = c[m][nt][1], c2 = c[m][nt][2], c3 = c[m][nt][3];
            float g0 = __shfl_xor_sync(0xffffffffu, c0, 1);
            float g1 = __shfl_xor_sync(0xffffffffu, c1, 1);
            float g2 = __shfl_xor_sync(0xffffffffu, c2, 1);
            float g3 = __shfl_xor_sync(0xffffffffu, c3, 1);
            float q0 = even ? c0 : g2;
            float q1 = even ? c1 : g3;
            float q2 = even ? g0 : c2;
            float q3 = even ? g1 : c3;
            if (msrc >= 0)
                red4(out + (size_t)msrc * 64 + nt * 8 + colbase, q0, q1, q2, q3);
        }
    }
#endif
}

extern "C" void kernel_launch(void* const* d_in, const int* in_sizes, int n_in,
                              void* d_out, int out_size) {
    const float* atom  = (const float*)d_in[0];
    const float* bondf = (const float*)d_in[1];
    const int*   pair  = (const int*)d_in[2];
    const float* K     = (const float*)d_in[3];
    const float* bias  = (const float*)d_in[4];
    float* out = (float*)d_out;

    int n_edges = in_sizes[2] / 2;
    int n_out4  = out_size / 4;

    zero_pack<<<(n_out4 + 255) / 256, 256>>>(K, bias, (float4*)out, n_out4);

    int grid = (n_edges + TM - 1) / TM;
    edge_main<<<grid, 256>>>(atom, bondf, pair, out, n_edges);
}

// round 9
// speedup vs baseline: 2.6269x; 1.0244x over previous
#include <cuda_runtime.h>
#include <cuda_fp16.h>
#include <cstdint>

#define TM      256
#define NBLK    17
// ---- fallback (mma.sync) W layout: per-lane-contiguous, pitch 68 ----
#define SLOTP   68
#define WBLK_U  (32 * SLOTP)        // 2176 uints per block
#define WBLK_V4 (WBLK_U / 4)        // 544
// ---- tcgen05 W layout: SW128 blocked-atom f16 image, 8 KB per block ----
#define TCBLK_U  2048
#define TCBLK_V4 512

__device__ uint4 W_img[NBLK * WBLK_V4];   // fallback image
__device__ uint4 W_tc [NBLK * TCBLK_V4];  // tcgen05 image

// ---------------- shared helpers ----------------
static __device__ __forceinline__ void cp_async16(uint32_t s, const void* g) {
    asm volatile("cp.async.cg.shared.global [%0], [%1], 16;" :: "r"(s), "l"(g));
}
static __device__ __forceinline__ uint32_t smem_u32(const void* p) {
    uint32_t a;
    asm("{ .reg .u64 t; cvta.to.shared.u64 t, %1; cvt.u32.u64 %0, t; }" : "=r"(a) : "l"(p));
    return a;
}
static __device__ __forceinline__ uint32_t h2u(__half2 h) {
    return *reinterpret_cast<uint32_t*>(&h);
}
static __device__ __forceinline__ __half2 u2h(uint32_t u) {
    return *reinterpret_cast<__half2*>(&u);
}
static __device__ __forceinline__ void red4(float* p, float a, float b, float c, float d) {
    asm volatile("red.global.add.v4.f32 [%0], {%1, %2, %3, %4};"
                 :: "l"(p), "f"(a), "f"(b), "f"(c), "f"(d) : "memory");
}
static __device__ __forceinline__ void mma16816(float* c, uint32_t a0, uint32_t a1,
                                                uint32_t a2, uint32_t a3,
                                                uint32_t b0, uint32_t b1) {
    asm volatile(
        "mma.sync.aligned.m16n8k16.row.col.f32.f16.f16.f32 "
        "{%0,%1,%2,%3}, {%4,%5,%6,%7}, {%8,%9}, {%0,%1,%2,%3};"
        : "+f"(c[0]), "+f"(c[1]), "+f"(c[2]), "+f"(c[3])
        : "r"(a0), "r"(a1), "r"(a2), "r"(a3), "r"(b0), "r"(b1));
}

// ---------------- tcgen05 helpers ----------------
#if defined(__CUDA_ARCH__) && defined(__CUDA_ARCH_FEAT_SM103_ALL)
#define TC_IDESC ((1u << 4) | (8u << 17) | (8u << 24))   // kind::f16: fp16 in, f32 acc, M=128, N=64
#define DBASE ((2ull << 61) | (1ull << 46) | (64ull << 32) | (1ull << 16))  // SW128, v1, SBO=64, LBO=1

static __device__ __forceinline__ bool elect1() {
    uint32_t p;
    asm volatile("{ .reg .pred P; elect.sync _|P, 0xFFFFFFFF; selp.b32 %0, 1, 0, P; }" : "=r"(p));
    return p != 0;
}
static __device__ __forceinline__ void mbar_init(uint32_t a, uint32_t c) {
    asm volatile("mbarrier.init.shared.b64 [%0], %1;" :: "r"(a), "r"(c) : "memory");
}
static __device__ __forceinline__ void mbar_wait(uint32_t a, uint32_t ph) {
    asm volatile(
        "{ .reg .pred P;\n"
        "LW_%=:\n"
        "mbarrier.try_wait.parity.acquire.cta.shared::cta.b64 P, [%0], %1, 0x989680;\n"
        "@!P bra LW_%=;\n"
        "}" :: "r"(a), "r"(ph) : "memory");
}
static __device__ __forceinline__ void tc_mma_f16(uint32_t d, uint32_t a, uint64_t bd,
                                                  uint32_t en) {
    asm volatile(
        "{ .reg .pred p; setp.ne.u32 p, %5, 0;\n"
        "tcgen05.mma.cta_group::1.kind::f16 [%0], [%1], %2, %3, {%4, %4, %4, %4}, p;\n"
        "}"
        :: "r"(d), "r"(a), "l"(bd), "r"(TC_IDESC), "r"(0u), "r"(en) : "memory");
}
static __device__ __forceinline__ void tmem_st32(uint32_t addr, const uint32_t* r) {
    asm volatile(
        "tcgen05.st.sync.aligned.32x32b.x32.b32 [%0], "
        "{%1,%2,%3,%4,%5,%6,%7,%8,%9,%10,%11,%12,%13,%14,%15,%16,"
        "%17,%18,%19,%20,%21,%22,%23,%24,%25,%26,%27,%28,%29,%30,%31,%32};"
        :: "r"(addr),
           "r"(r[0]),  "r"(r[1]),  "r"(r[2]),  "r"(r[3]),
           "r"(r[4]),  "r"(r[5]),  "r"(r[6]),  "r"(r[7]),
           "r"(r[8]),  "r"(r[9]),  "r"(r[10]), "r"(r[11]),
           "r"(r[12]), "r"(r[13]), "r"(r[14]), "r"(r[15]),
           "r"(r[16]), "r"(r[17]), "r"(r[18]), "r"(r[19]),
           "r"(r[20]), "r"(r[21]), "r"(r[22]), "r"(r[23]),
           "r"(r[24]), "r"(r[25]), "r"(r[26]), "r"(r[27]),
           "r"(r[28]), "r"(r[29]), "r"(r[30]), "r"(r[31])
        : "memory");
}
static __device__ __forceinline__ void tmem_ld32(uint32_t* r, uint32_t addr) {
    asm volatile(
        "tcgen05.ld.sync.aligned.32x32b.x32.b32 "
        "{%0,%1,%2,%3,%4,%5,%6,%7,%8,%9,%10,%11,%12,%13,%14,%15,"
        "%16,%17,%18,%19,%20,%21,%22,%23,%24,%25,%26,%27,%28,%29,%30,%31}, [%32];"
        : "=r"(r[0]),  "=r"(r[1]),  "=r"(r[2]),  "=r"(r[3]),
          "=r"(r[4]),  "=r"(r[5]),  "=r"(r[6]),  "=r"(r[7]),
          "=r"(r[8]),  "=r"(r[9]),  "=r"(r[10]), "=r"(r[11]),
          "=r"(r[12]), "=r"(r[13]), "=r"(r[14]), "=r"(r[15]),
          "=r"(r[16]), "=r"(r[17]), "=r"(r[18]), "=r"(r[19]),
          "=r"(r[20]), "=r"(r[21]), "=r"(r[22]), "=r"(r[23]),
          "=r"(r[24]), "=r"(r[25]), "=r"(r[26]), "=r"(r[27]),
          "=r"(r[28]), "=r"(r[29]), "=r"(r[30]), "=r"(r[31])
        : "r"(addr));
}
#endif

// ---------------- zero output + pack both W images ----------------
__global__ void __launch_bounds__(256)
zero_pack(const float* __restrict__ K, const float* __restrict__ bias,
          float4* __restrict__ out4, int n_out4) {
    int idx = blockIdx.x * blockDim.x + threadIdx.x;
    if (idx < n_out4) out4[idx] = make_float4(0.f, 0.f, 0.f, 0.f);
    if (idx < NBLK * 2048) {
        int b = idx >> 11, r = idx & 2047;
        // fallback image: per-lane-contiguous values
        {
            int slot = r >> 6, v = r & 63;
            int gid = slot >> 2, tig = slot & 3;
            int s = v >> 4, r2 = v & 15, nt = r2 >> 1, h = r2 & 1;
            int p = 8 * s + tig + 4 * h;
            int n = nt * 8 + gid;
            float v0, v1;
            if (b < 16) { v0 = K[b * 4096 + n * 64 + 2 * p]; v1 = K[b * 4096 + n * 64 + 2 * p + 1]; }
            else        { v0 = bias[n * 64 + 2 * p];          v1 = bias[n * 64 + 2 * p + 1]; }
            ((uint32_t*)W_img)[b * WBLK_U + slot * SLOTP + v] = h2u(__floats2half2_rn(v0, v1));
        }
        // tcgen05 image: B[n][k] f16, SW128 atoms (8 rows x 128 B), K=64 f16 = one atom column
        {
            int n = r >> 5, p = r & 31;
            float v0, v1;
            if (b < 16) { v0 = K[b * 4096 + n * 64 + 2 * p]; v1 = K[b * 4096 + n * 64 + 2 * p + 1]; }
            else        { v0 = bias[n * 64 + 2 * p];          v1 = bias[n * 64 + 2 * p + 1]; }
            int byte = (n >> 3) * 1024 + (n & 7) * 128 + p * 4;
            int sw = byte ^ ((byte >> 3) & 0x70);
            ((uint32_t*)W_tc)[b * TCBLK_U + (sw >> 2)] = h2u(__floats2half2_rn(v0, v1));
        }
    }
}

__global__ void __launch_bounds__(256, 2)
edge_main(const float* __restrict__ atom, const float* __restrict__ bondf,
          const int* __restrict__ pair, float* __restrict__ out, int n_edges)
{
    const int tid  = threadIdx.x;
    const int warp = tid >> 5;
    const int e0   = blockIdx.x * TM;

#if defined(__CUDA_ARCH__) && defined(__CUDA_ARCH_FEAT_SM103_ALL)
    // ================= tcgen05 path (sm_103a cubin), software-pipelined =================
    // Two mbarriers (even/odd b) keep per-barrier wait lag <= 1: the wait for MMA_{b-1}
    // on MB[(b-1)&1] happens before the next commit to that SAME barrier (at b+1), so
    // parity aliasing (the round-8 deadlock) cannot occur.
    __shared__ __align__(1024) uint32_t Wsm[3][TCBLK_U];   // 24576 B, triple-buffered
    __shared__ uint32_t bond_h[NBLK * TM];                 // 17408 B
    __shared__ __align__(16) uint32_t hdr[8];              // [0] tmem ptr | [2..3] MB0 | [4..5] MB1

    const uint32_t TP  = smem_u32(&hdr[0]);
    const uint32_t MB0 = smem_u32(&hdr[2]);
    const uint32_t MB1 = smem_u32(&hdr[4]);

    const int sub = tid >> 7;          // M-subtile (two 128-row tiles per CTA)
    const int row = tid & 127;
    const int e   = e0 + tid;

    // Alloc THEN relinquish, both on warp 0, sequential in program order.
    if (warp == 0) {
        asm volatile("tcgen05.alloc.cta_group::1.sync.aligned.shared::cta.b32 [%0], %1;"
                     :: "r"(TP), "r"(256u) : "memory");
        asm volatile("tcgen05.relinquish_alloc_permit.cta_group::1.sync.aligned;");
    }
    if (tid == 0) { mbar_init(MB0, 1); mbar_init(MB1, 1); }

    // Stage W_0, W_1 (groups 0, 1).
    #pragma unroll
    for (int g = 0; g < 2; g++) {
        for (int i = tid; i < TCBLK_V4; i += 256)
            cp_async16(smem_u32(&Wsm[g][0]) + i * 16, W_tc + g * TCBLK_V4 + i);
        asm volatile("cp.async.commit_group;");
    }

    // Stage bond (dup half2); src in register; gather neighbor row -> 32 half2 regs.
    int src = -1, nbr = 0;
    {
        float4 q0 = {0,0,0,0}, q1 = q0, q2 = q0, q3 = q0;
        float one = 0.f;
        if (e < n_edges) {
            int2 pr = ((const int2*)pair)[e];
            src = pr.x; nbr = pr.y; one = 1.f;
            const float4* bp = (const float4*)(bondf + (size_t)e * 16);
            q0 = bp[0]; q1 = bp[1]; q2 = bp[2]; q3 = bp[3];
        }
        const float bv[16] = {q0.x,q0.y,q0.z,q0.w, q1.x,q1.y,q1.z,q1.w,
                              q2.x,q2.y,q2.z,q2.w, q3.x,q3.y,q3.z,q3.w};
        #pragma unroll
        for (int b = 0; b < 16; b++) bond_h[b * TM + tid] = h2u(__float2half2_rn(bv[b]));
        bond_h[16 * TM + tid] = h2u(__float2half2_rn(one));
    }
    __half2 nb[32];
    {
        const float4* ap = (const float4*)(atom + (size_t)nbr * 64);
        #pragma unroll
        for (int q = 0; q < 16; q++) {
            float4 v = __ldg(ap + q);
            nb[2 * q]     = __floats2half2_rn(v.x, v.y);
            nb[2 * q + 1] = __floats2half2_rn(v.z, v.w);
        }
    }
    __syncthreads();   // alloc result, mbar init, bond visible

    uint32_t tmem;
    asm volatile("ld.shared.b32 %0, [%1];" : "=r"(tmem) : "r"(TP));
    const uint32_t Dt = tmem;                 // D: sub0 cols 0..63, sub1 cols 64..127
    const uint32_t A0 = tmem + 128;           // A double buffer: 64 cols each
    const uint32_t A1 = tmem + 192;
    const uint32_t lane_off = (uint32_t)(row >> 5) << 21;
    const uint32_t aoff = (uint32_t)sub * 32 + lane_off;

    // Prologue: build Z_0 -> A0.
    {
        __half2 bh = u2h(bond_h[tid]);
        uint32_t z[32];
        #pragma unroll
        for (int j = 0; j < 32; j++) z[j] = h2u(__hmul2(nb[j], bh));
        tmem_st32(A0 + aoff, z);
        asm volatile("tcgen05.wait::st.sync.aligned;" ::: "memory");
        asm volatile("tcgen05.fence::before_thread_sync;" ::: "memory");
    }

    #pragma unroll 1
    for (int b = 0; b < NBLK; b++) {
        asm volatile("cp.async.wait_group 1;" ::: "memory");   // W_b resident (W_{b+1} may fly)
        asm volatile("fence.proxy.async.shared::cta;" ::: "memory");
        __syncthreads();   // Z_b stores (all warps) + W_b visible

        // Issue MMA_b -> MB[b&1]; overlaps Z_{b+1} build and W_{b+2} staging below.
        if (warp == 0) {
            asm volatile("tcgen05.fence::after_thread_sync;" ::: "memory");
            if (elect1()) {
                int wsel = b - (b / 3) * 3;   // b % 3
                uint64_t bd = DBASE | (uint64_t)((smem_u32(&Wsm[wsel][0]) >> 4) & 0x3FFF);
                uint32_t aa = (b & 1) ? A1 : A0;
                #pragma unroll
                for (int k = 0; k < 4; k++) {
                    uint32_t en = (b > 0 || k > 0) ? 1u : 0u;
                    tc_mma_f16(Dt,      aa      + k * 8, bd + k * 2, en);
                    tc_mma_f16(Dt + 64, aa + 32 + k * 8, bd + k * 2, en);
                }
                asm volatile(
                    "tcgen05.commit.cta_group::1.mbarrier::arrive::one.shared::cluster.b64 [%0];"
                    :: "r"((b & 1) ? MB1 : MB0) : "memory");
            }
        }

        if (b + 1 < NBLK) {
            if (b >= 1) {
                // Wait MMA_{b-1} on its own barrier: phase (b-1)/2, parity ((b-1)>>1)&1.
                // Frees A[(b+1)&1] and Wsm[(b+2)%3].
                mbar_wait((b & 1) ? MB0 : MB1, ((b - 1) >> 1) & 1);
                asm volatile("tcgen05.fence::after_thread_sync;" ::: "memory");
            }
            {
                __half2 bh = u2h(bond_h[(b + 1) * TM + tid]);
                uint32_t z[32];
                #pragma unroll
                for (int j = 0; j < 32; j++) z[j] = h2u(__hmul2(nb[j], bh));
                tmem_st32(((b & 1) ? A0 : A1) + aoff, z);
                asm volatile("tcgen05.wait::st.sync.aligned;" ::: "memory");
                asm volatile("tcgen05.fence::before_thread_sync;" ::: "memory");
            }
            if (b + 2 < NBLK) {
                int dst = (b + 2) - ((b + 2) / 3) * 3;
                uint32_t da = smem_u32(&Wsm[dst][0]);
                for (int i = tid; i < TCBLK_V4; i += 256)
                    cp_async16(da + i * 16, W_tc + (b + 2) * TCBLK_V4 + i);
            }
        }
        asm volatile("cp.async.commit_group;");   // exactly one group per iteration
    }

    // Wait MMA_16 on MB0: phase 8, parity 0. (MB0 in-loop waits consumed phases 0..7;
    // completions cannot exceed 9 -> no aliasing. MMA_15 completes before MMA_16 in order.)
    mbar_wait(MB0, 0);
    asm volatile("tcgen05.fence::after_thread_sync;" ::: "memory");

    // Readout + segment-sum RED.
    {
        uint32_t d0[32], d1[32];
        tmem_ld32(d0, Dt + (uint32_t)sub * 64 + lane_off);
        tmem_ld32(d1, Dt + (uint32_t)sub * 64 + 32 + lane_off);
        asm volatile("tcgen05.wait::ld.sync.aligned;" ::: "memory");
        if (src >= 0) {
            float* op = out + (size_t)src * 64;
            #pragma unroll
            for (int q = 0; q < 8; q++)
                red4(op + 4 * q, __uint_as_float(d0[4*q]),   __uint_as_float(d0[4*q+1]),
                                 __uint_as_float(d0[4*q+2]), __uint_as_float(d0[4*q+3]));
            #pragma unroll
            for (int q = 0; q < 8; q++)
                red4(op + 32 + 4 * q, __uint_as_float(d1[4*q]),   __uint_as_float(d1[4*q+1]),
                                      __uint_as_float(d1[4*q+2]), __uint_as_float(d1[4*q+3]));
        }
    }
    __syncthreads();
    if (warp == 0)
        asm volatile("tcgen05.dealloc.cta_group::1.sync.aligned.b32 %0, %1;"
                     :: "r"(tmem), "r"(256u));
#else
    // ================= fallback: mma.sync fp16 (compute_103 cubin) =================
    __shared__ uint32_t Wall[3 * WBLK_U];       // 26112 B
    __shared__ uint32_t bond_h[NBLK * TM];      // 17408 B
    __shared__ int      src_s[TM];              // 1024 B

    const int lane = tid & 31;
    const int gid  = lane >> 2, tig = lane & 3;

    #pragma unroll
    for (int g = 0; g < 2; g++) {
        for (int i = tid; i < WBLK_V4; i += 256)
            cp_async16(smem_u32(Wall) + (g * WBLK_V4 + i) * 16, W_img + g * WBLK_V4 + i);
        asm volatile("cp.async.commit_group;");
    }

    {
        int e = e0 + tid;
        int src = -1;
        float4 q0 = {0,0,0,0}, q1 = q0, q2 = q0, q3 = q0;
        float one = 0.f;
        if (e < n_edges) {
            src = ((const int2*)pair)[e].x;
            one = 1.f;
            const float4* bp = (const float4*)(bondf + (size_t)e * 16);
            q0 = bp[0]; q1 = bp[1]; q2 = bp[2]; q3 = bp[3];
        }
        src_s[tid] = src;
        const float bv[16] = {q0.x,q0.y,q0.z,q0.w, q1.x,q1.y,q1.z,q1.w,
                              q2.x,q2.y,q2.z,q2.w, q3.x,q3.y,q3.z,q3.w};
        #pragma unroll
        for (int b = 0; b < 16; b++) bond_h[b * TM + tid] = h2u(__float2half2_rn(bv[b]));
        bond_h[16 * TM + tid] = h2u(__float2half2_rn(one));
    }

    const int row0 = warp * 32 + gid;
    __half2 nb[4][8];
    #pragma unroll
    for (int r = 0; r < 4; r++) {
        int e = e0 + row0 + 8 * r;
        int nbr = (e < n_edges) ? ((const int2*)pair)[e].y : 0;
        const float2* ap = (const float2*)(atom + (size_t)nbr * 64);
        #pragma unroll
        for (int q = 0; q < 8; q++) {
            float2 v = __ldg(ap + 4 * q + tig);
            nb[r][q] = __floats2half2_rn(v.x, v.y);
        }
    }

    float c[2][8][4];
    #pragma unroll
    for (int m = 0; m < 2; m++)
        #pragma unroll
        for (int nt = 0; nt < 8; nt++)
            c[m][nt][0] = c[m][nt][1] = c[m][nt][2] = c[m][nt][3] = 0.f;

    int wb = 0;   // b % 3
    for (int b = 0; b < NBLK; b++) {
        asm volatile("cp.async.wait_group 1;" ::: "memory");
        __syncthreads();

        if (b + 2 < NBLK) {
            int dst = wb + 2 - ((wb + 2 >= 3) ? 3 : 0);
            for (int i = tid; i < WBLK_V4; i += 256)
                cp_async16(smem_u32(Wall) + (dst * WBLK_V4 + i) * 16,
                           W_img + (b + 2) * WBLK_V4 + i);
        }
        asm volatile("cp.async.commit_group;");

        __half2 bh0 = u2h(bond_h[b * TM + row0]);
        __half2 bh1 = u2h(bond_h[b * TM + row0 + 8]);
        __half2 bh2 = u2h(bond_h[b * TM + row0 + 16]);
        __half2 bh3 = u2h(bond_h[b * TM + row0 + 24]);

        const uint32_t* wbase = Wall + wb * WBLK_U + lane * SLOTP;
        #pragma unroll
        for (int s = 0; s < 4; s++) {
            uint4 q0 = *(const uint4*)(wbase + s * 16);
            uint4 q1 = *(const uint4*)(wbase + s * 16 + 4);
            uint4 q2 = *(const uint4*)(wbase + s * 16 + 8);
            uint4 q3 = *(const uint4*)(wbase + s * 16 + 12);

            uint32_t a00 = h2u(__hmul2(nb[0][2*s],   bh0));
            uint32_t a01 = h2u(__hmul2(nb[1][2*s],   bh1));
            uint32_t a02 = h2u(__hmul2(nb[0][2*s+1], bh0));
            uint32_t a03 = h2u(__hmul2(nb[1][2*s+1], bh1));
            uint32_t a10 = h2u(__hmul2(nb[2][2*s],   bh2));
            uint32_t a11 = h2u(__hmul2(nb[3][2*s],   bh3));
            uint32_t a12 = h2u(__hmul2(nb[2][2*s+1], bh2));
            uint32_t a13 = h2u(__hmul2(nb[3][2*s+1], bh3));

            mma16816(c[0][0], a00, a01, a02, a03, q0.x, q0.y);
            mma16816(c[1][0], a10, a11, a12, a13, q0.x, q0.y);
            mma16816(c[0][1], a00, a01, a02, a03, q0.z, q0.w);
            mma16816(c[1][1], a10, a11, a12, a13, q0.z, q0.w);
            mma16816(c[0][2], a00, a01, a02, a03, q1.x, q1.y);
            mma16816(c[1][2], a10, a11, a12, a13, q1.x, q1.y);
            mma16816(c[0][3], a00, a01, a02, a03, q1.z, q1.w);
            mma16816(c[1][3], a10, a11, a12, a13, q1.z, q1.w);
            mma16816(c[0][4], a00, a01, a02, a03, q2.x, q2.y);
            mma16816(c[1][4], a10, a11, a12, a13, q2.x, q2.y);
            mma16816(c[0][5], a00, a01, a02, a03, q2.z, q2.w);
            mma16816(c[1][5], a10, a11, a12, a13, q2.z, q2.w);
            mma16816(c[0][6], a00, a01, a02, a03, q3.x, q3.y);
            mma16816(c[1][6], a10, a11, a12, a13, q3.x, q3.y);
            mma16816(c[0][7], a00, a01, a02, a03, q3.z, q3.w);
            mma16816(c[1][7], a10, a11, a12, a13, q3.z, q3.w);
        }
        wb = (wb == 2) ? 0 : wb + 1;
    }

    const bool even = (tig & 1) == 0;
    #pragma unroll
    for (int m = 0; m < 2; m++) {
        int srcA = src_s[warp * 32 + m * 16 + gid];
        int srcB = src_s[warp * 32 + m * 16 + gid + 8];
        int msrc = even ? srcA : srcB;
        int colbase = 4 * (tig >> 1);
        #pragma unroll
        for (int nt = 0; nt < 8; nt++) {
            float c0 = c[m][nt][0], c1 = c[m][nt][1], c2 = c[m][nt][2], c3 = c[m][nt][3];
            float g0 = __shfl_xor_sync(0xffffffffu, c0, 1);
            float g1 = __shfl_xor_sync(0xffffffffu, c1, 1);
            float g2 = __shfl_xor_sync(0xffffffffu, c2, 1);
            float g3 = __shfl_xor_sync(0xffffffffu, c3, 1);
            float q0 = even ? c0 : g2;
            float q1 = even ? c1 : g3;
            float q2 = even ? g0 : c2;
            float q3 = even ? g1 : c3;
            if (msrc >= 0)
                red4(out + (size_t)msrc * 64 + nt * 8 + colbase, q0, q1, q2, q3);
        }
    }
#endif
}

extern "C" void kernel_launch(void* const* d_in, const int* in_sizes, int n_in,
                              void* d_out, int out_size) {
    const float* atom  = (const float*)d_in[0];
    const float* bondf = (const float*)d_in[1];
    const int*   pair  = (const int*)d_in[2];
    const float* K     = (const float*)d_in[3];
    const float* bias  = (const float*)d_in[4];
    float* out = (float*)d_out;

    int n_edges = in_sizes[2] / 2;
    int n_out4  = out_size / 4;

    zero_pack<<<(n_out4 + 255) / 256, 256>>>(K, bias, (float4*)out, n_out4);

    int grid = (n_edges + TM - 1) / TM;
    edge_main<<<grid, 256>>>(atom, bondf, pair, out, n_edges);
}